// round 4
// baseline (speedup 1.0000x reference)
#include <cuda_runtime.h>
#include <math.h>

#define BATCH 16384
#define FEAT  2048
#define F4    (FEAT / 4)          // 512 float4 per row
#define WARPS_PER_BLOCK 8
#define THREADS (WARPS_PER_BLOCK * 32)
#define GRID 1024                 // single wave on 148 SMs
#define TOTAL_WARPS (GRID * WARPS_PER_BLOCK)   // 8192
#define ROWS_PER_WARP (BATCH / TOTAL_WARPS)    // 2

__device__ float        g_partials[GRID];
__device__ unsigned int g_done = 0;

__device__ __forceinline__ float4 ldcs4(const float4* p) {
    return __ldcs(p);   // streaming (evict-first) — data is read exactly once
}

__global__ __launch_bounds__(THREADS)
void triplet_loss_kernel(const float4* __restrict__ anchor,
                         const float4* __restrict__ positive,
                         const float4* __restrict__ negative,
                         float* __restrict__ out) {
    const int lane = threadIdx.x & 31;
    const int warp_in_block = threadIdx.x >> 5;
    const int gwarp = blockIdx.x * WARPS_PER_BLOCK + warp_in_block;  // 0..8191

    float warp_acc = 0.0f;  // meaningful on lane 0 only

    #pragma unroll
    for (int r = 0; r < ROWS_PER_WARP; r++) {
        const int row = gwarp + r * TOTAL_WARPS;   // w and w + 8192

        const float4* __restrict__ ar = anchor   + (size_t)row * F4;
        const float4* __restrict__ pr = positive + (size_t)row * F4;
        const float4* __restrict__ nr = negative + (size_t)row * F4;

        float dp = 0.0f;  // sum (a-p)^2
        float dn = 0.0f;  // sum (a-n)^2

        // 512 float4 per row, 32 lanes -> 16 iterations per lane.
        // unroll 8: 24 LDG.128 per burst — enough MLP, less queue spread.
        #pragma unroll 8
        for (int i = lane; i < F4; i += 32) {
            float4 av = ldcs4(ar + i);
            float4 pv = ldcs4(pr + i);
            float4 nv = ldcs4(nr + i);

            float d;
            d = av.x - pv.x; dp = fmaf(d, d, dp);
            d = av.y - pv.y; dp = fmaf(d, d, dp);
            d = av.z - pv.z; dp = fmaf(d, d, dp);
            d = av.w - pv.w; dp = fmaf(d, d, dp);

            d = av.x - nv.x; dn = fmaf(d, d, dn);
            d = av.y - nv.y; dn = fmaf(d, d, dn);
            d = av.z - nv.z; dn = fmaf(d, d, dn);
            d = av.w - nv.w; dn = fmaf(d, d, dn);
        }

        // Warp reduction
        #pragma unroll
        for (int off = 16; off > 0; off >>= 1) {
            dp += __shfl_xor_sync(0xFFFFFFFFu, dp, off);
            dn += __shfl_xor_sync(0xFFFFFFFFu, dn, off);
        }

        if (lane == 0) {
            float loss = sqrtf(dp) - sqrtf(dn) + 1.0f;      // MARGIN = 1.0
            warp_acc += fmaxf(loss, 0.0f) * (1.0f / (float)BATCH);
        }
    }

    __shared__ float partial[WARPS_PER_BLOCK];
    __shared__ bool am_last;
    if (lane == 0) partial[warp_in_block] = warp_acc;
    __syncthreads();

    // Per-block sum -> global partials; ticket to detect last block.
    if (threadIdx.x == 0) {
        float acc = 0.0f;
        #pragma unroll
        for (int w = 0; w < WARPS_PER_BLOCK; w++) acc += partial[w];
        g_partials[blockIdx.x] = acc;
        __threadfence();
        unsigned int t = atomicAdd(&g_done, 1u);
        am_last = (t == GRID - 1);
    }
    __syncthreads();

    // Last block reduces all 1024 partials and writes the output.
    if (am_last) {
        float acc = 0.0f;
        #pragma unroll
        for (int i = threadIdx.x; i < GRID; i += THREADS)
            acc += __ldcg(&g_partials[i]);      // L2-coherent read

        #pragma unroll
        for (int off = 16; off > 0; off >>= 1)
            acc += __shfl_xor_sync(0xFFFFFFFFu, acc, off);

        if (lane == 0) partial[warp_in_block] = acc;
        __syncthreads();

        if (threadIdx.x == 0) {
            float total = 0.0f;
            #pragma unroll
            for (int w = 0; w < WARPS_PER_BLOCK; w++) total += partial[w];
            *out = total;
            g_done = 0;          // reset for next graph replay (deterministic)
        }
    }
}

extern "C" void kernel_launch(void* const* d_in, const int* in_sizes, int n_in,
                              void* d_out, int out_size) {
    const float4* anchor   = (const float4*)d_in[0];
    const float4* positive = (const float4*)d_in[1];
    const float4* negative = (const float4*)d_in[2];
    float* out = (float*)d_out;

    triplet_loss_kernel<<<GRID, THREADS>>>(anchor, positive, negative, out);
}

// round 8
// speedup vs baseline: 1.0365x; 1.0365x over previous
#include <cuda_runtime.h>
#include <math.h>

#define BATCH 16384
#define FEAT  2048
#define F4    (FEAT / 4)          // 512 float4 per row
#define WARPS_PER_BLOCK 8
#define THREADS (WARPS_PER_BLOCK * 32)
#define GRID 1024                 // single wave on 148 SMs
#define TOTAL_WARPS (GRID * WARPS_PER_BLOCK)   // 8192
#define ROWS_PER_WARP (BATCH / TOTAL_WARPS)    // 2

__device__ float        g_partials[GRID];
__device__ unsigned int g_done = 0;

__device__ __forceinline__ float4 ldcs4(const float4* p) {
    return __ldcs(p);   // streaming (evict-first) — data is read exactly once
}

__global__ __launch_bounds__(THREADS, 7)
void triplet_loss_kernel(const float4* __restrict__ anchor,
                         const float4* __restrict__ positive,
                         const float4* __restrict__ negative,
                         float* __restrict__ out) {
    const int lane = threadIdx.x & 31;
    const int warp_in_block = threadIdx.x >> 5;
    const int gwarp = blockIdx.x * WARPS_PER_BLOCK + warp_in_block;  // 0..8191

    float warp_acc = 0.0f;  // meaningful on lane 0 only

    #pragma unroll
    for (int r = 0; r < ROWS_PER_WARP; r++) {
        const int row = gwarp + r * TOTAL_WARPS;   // w and w + 8192

        const float4* __restrict__ ar = anchor   + (size_t)row * F4;
        const float4* __restrict__ pr = positive + (size_t)row * F4;
        const float4* __restrict__ nr = negative + (size_t)row * F4;

        float dp = 0.0f;  // sum (a-p)^2
        float dn = 0.0f;  // sum (a-n)^2

        // 512 float4 per row, 32 lanes -> 16 iterations per lane.
        #pragma unroll 16
        for (int i = lane; i < F4; i += 32) {
            float4 av = ldcs4(ar + i);
            float4 pv = ldcs4(pr + i);
            float4 nv = ldcs4(nr + i);

            float d;
            d = av.x - pv.x; dp = fmaf(d, d, dp);
            d = av.y - pv.y; dp = fmaf(d, d, dp);
            d = av.z - pv.z; dp = fmaf(d, d, dp);
            d = av.w - pv.w; dp = fmaf(d, d, dp);

            d = av.x - nv.x; dn = fmaf(d, d, dn);
            d = av.y - nv.y; dn = fmaf(d, d, dn);
            d = av.z - nv.z; dn = fmaf(d, d, dn);
            d = av.w - nv.w; dn = fmaf(d, d, dn);
        }

        // Warp reduction
        #pragma unroll
        for (int off = 16; off > 0; off >>= 1) {
            dp += __shfl_xor_sync(0xFFFFFFFFu, dp, off);
            dn += __shfl_xor_sync(0xFFFFFFFFu, dn, off);
        }

        if (lane == 0) {
            float loss = sqrtf(dp) - sqrtf(dn) + 1.0f;      // MARGIN = 1.0
            warp_acc += fmaxf(loss, 0.0f) * (1.0f / (float)BATCH);
        }
    }

    __shared__ float partial[WARPS_PER_BLOCK];
    __shared__ bool am_last;
    if (lane == 0) partial[warp_in_block] = warp_acc;
    __syncthreads();

    // Per-block sum -> global partials; ticket to detect last block.
    if (threadIdx.x == 0) {
        float acc = 0.0f;
        #pragma unroll
        for (int w = 0; w < WARPS_PER_BLOCK; w++) acc += partial[w];
        g_partials[blockIdx.x] = acc;
        __threadfence();
        unsigned int t = atomicAdd(&g_done, 1u);
        am_last = (t == GRID - 1);
    }
    __syncthreads();

    // Last block reduces all 1024 partials and writes the output.
    if (am_last) {
        float acc = 0.0f;
        #pragma unroll 4
        for (int i = threadIdx.x; i < GRID; i += THREADS)
            acc += __ldcg(&g_partials[i]);      // L2-coherent read

        #pragma unroll
        for (int off = 16; off > 0; off >>= 1)
            acc += __shfl_xor_sync(0xFFFFFFFFu, acc, off);

        if (lane == 0) partial[warp_in_block] = acc;
        __syncthreads();

        if (threadIdx.x == 0) {
            float total = 0.0f;
            #pragma unroll
            for (int w = 0; w < WARPS_PER_BLOCK; w++) total += partial[w];
            *out = total;
            g_done = 0;          // reset for next graph replay (deterministic)
        }
    }
}

extern "C" void kernel_launch(void* const* d_in, const int* in_sizes, int n_in,
                              void* d_out, int out_size) {
    const float4* anchor   = (const float4*)d_in[0];
    const float4* positive = (const float4*)d_in[1];
    const float4* negative = (const float4*)d_in[2];
    float* out = (float*)d_out;

    triplet_loss_kernel<<<GRID, THREADS>>>(anchor, positive, negative, out);
}

// round 9
// speedup vs baseline: 1.0473x; 1.0103x over previous
#include <cuda_runtime.h>
#include <math.h>

#define BATCH 16384
#define FEAT  2048
#define F4    (FEAT / 4)          // 512 float4 per row
#define WARPS_PER_BLOCK 8
#define THREADS (WARPS_PER_BLOCK * 32)
#define GRID 1024                 // single wave on 148 SMs
#define TOTAL_WARPS (GRID * WARPS_PER_BLOCK)   // 8192
#define ROWS_PER_WARP (BATCH / TOTAL_WARPS)    // 2

__device__ float        g_sum  = 0.0f;
__device__ unsigned int g_done = 0;

__device__ __forceinline__ float4 ldcs4(const float4* p) {
    return __ldcs(p);   // streaming (evict-first) — data is read exactly once
}

__global__ __launch_bounds__(THREADS, 7)
void triplet_loss_kernel(const float4* __restrict__ anchor,
                         const float4* __restrict__ positive,
                         const float4* __restrict__ negative,
                         float* __restrict__ out) {
    const int lane = threadIdx.x & 31;
    const int warp_in_block = threadIdx.x >> 5;
    const int gwarp = blockIdx.x * WARPS_PER_BLOCK + warp_in_block;  // 0..8191

    float warp_acc = 0.0f;  // meaningful on lane 0 only

    #pragma unroll
    for (int r = 0; r < ROWS_PER_WARP; r++) {
        const int row = gwarp + r * TOTAL_WARPS;   // w and w + 8192

        const float4* __restrict__ ar = anchor   + (size_t)row * F4;
        const float4* __restrict__ pr = positive + (size_t)row * F4;
        const float4* __restrict__ nr = negative + (size_t)row * F4;

        float dp = 0.0f;  // sum (a-p)^2
        float dn = 0.0f;  // sum (a-n)^2

        // 512 float4 per row, 32 lanes -> 16 iterations per lane.
        #pragma unroll 16
        for (int i = lane; i < F4; i += 32) {
            float4 av = ldcs4(ar + i);
            float4 pv = ldcs4(pr + i);
            float4 nv = ldcs4(nr + i);

            float d;
            d = av.x - pv.x; dp = fmaf(d, d, dp);
            d = av.y - pv.y; dp = fmaf(d, d, dp);
            d = av.z - pv.z; dp = fmaf(d, d, dp);
            d = av.w - pv.w; dp = fmaf(d, d, dp);

            d = av.x - nv.x; dn = fmaf(d, d, dn);
            d = av.y - nv.y; dn = fmaf(d, d, dn);
            d = av.z - nv.z; dn = fmaf(d, d, dn);
            d = av.w - nv.w; dn = fmaf(d, d, dn);
        }

        // Warp reduction
        #pragma unroll
        for (int off = 16; off > 0; off >>= 1) {
            dp += __shfl_xor_sync(0xFFFFFFFFu, dp, off);
            dn += __shfl_xor_sync(0xFFFFFFFFu, dn, off);
        }

        if (lane == 0) {
            float loss = sqrtf(dp) - sqrtf(dn) + 1.0f;      // MARGIN = 1.0
            warp_acc += fmaxf(loss, 0.0f) * (1.0f / (float)BATCH);
        }
    }

    __shared__ float partial[WARPS_PER_BLOCK];
    if (lane == 0) partial[warp_in_block] = warp_acc;
    __syncthreads();

    // Thread 0 only: accumulate into global sum, ticket, minimal-tail finalize.
    if (threadIdx.x == 0) {
        float acc = 0.0f;
        #pragma unroll
        for (int w = 0; w < WARPS_PER_BLOCK; w++) acc += partial[w];

        atomicAdd(&g_sum, acc);          // value-add (completes at L2)
        __threadfence();                 // order value-add before ticket
        unsigned int t = atomicAdd(&g_done, 1u);
        if (t == GRID - 1) {
            // All 1024 value-adds are L2-visible. Read total atomically.
            float total = atomicAdd(&g_sum, 0.0f);
            *out = total;
            __threadfence();
            g_sum  = 0.0f;               // reset for next graph replay
            g_done = 0;
        }
    }
}

extern "C" void kernel_launch(void* const* d_in, const int* in_sizes, int n_in,
                              void* d_out, int out_size) {
    const float4* anchor   = (const float4*)d_in[0];
    const float4* positive = (const float4*)d_in[1];
    const float4* negative = (const float4*)d_in[2];
    float* out = (float*)d_out;

    triplet_loss_kernel<<<GRID, THREADS>>>(anchor, positive, negative, out);
}

// round 10
// speedup vs baseline: 1.0603x; 1.0125x over previous
#include <cuda_runtime.h>
#include <math.h>

#define BATCH 16384
#define FEAT  2048
#define F4    (FEAT / 4)          // 512 float4 per row
#define WARPS_PER_BLOCK 8
#define THREADS (WARPS_PER_BLOCK * 32)
#define GRID 1024                 // single wave: 1024 <= 148 SMs * 7 blocks
#define TOTAL_WARPS (GRID * WARPS_PER_BLOCK)   // 8192
#define ROWS_PER_WARP (BATCH / TOTAL_WARPS)    // 2

__global__ void zero_out_kernel(float* out) {
    out[0] = 0.0f;
#if __CUDA_ARCH__ >= 900
    cudaTriggerProgrammaticLaunchCompletion();
#endif
}

__device__ __forceinline__ float4 ldcs4(const float4* p) {
    return __ldcs(p);   // streaming (evict-first) — data is read exactly once
}

__global__ __launch_bounds__(THREADS, 7)
void triplet_loss_kernel(const float4* __restrict__ anchor,
                         const float4* __restrict__ positive,
                         const float4* __restrict__ negative,
                         float* __restrict__ out) {
    const int lane = threadIdx.x & 31;
    const int warp_in_block = threadIdx.x >> 5;
    const int gwarp = blockIdx.x * WARPS_PER_BLOCK + warp_in_block;  // 0..8191

    float warp_acc = 0.0f;  // meaningful on lane 0 only

    #pragma unroll
    for (int r = 0; r < ROWS_PER_WARP; r++) {
        const int row = gwarp + r * TOTAL_WARPS;   // w and w + 8192

        const float4* __restrict__ ar = anchor   + (size_t)row * F4;
        const float4* __restrict__ pr = positive + (size_t)row * F4;
        const float4* __restrict__ nr = negative + (size_t)row * F4;

        float dp = 0.0f;  // sum (a-p)^2
        float dn = 0.0f;  // sum (a-n)^2

        // 512 float4 per row, 32 lanes -> 16 iterations per lane.
        #pragma unroll 16
        for (int i = lane; i < F4; i += 32) {
            float4 av = ldcs4(ar + i);
            float4 pv = ldcs4(pr + i);
            float4 nv = ldcs4(nr + i);

            float d;
            d = av.x - pv.x; dp = fmaf(d, d, dp);
            d = av.y - pv.y; dp = fmaf(d, d, dp);
            d = av.z - pv.z; dp = fmaf(d, d, dp);
            d = av.w - pv.w; dp = fmaf(d, d, dp);

            d = av.x - nv.x; dn = fmaf(d, d, dn);
            d = av.y - nv.y; dn = fmaf(d, d, dn);
            d = av.z - nv.z; dn = fmaf(d, d, dn);
            d = av.w - nv.w; dn = fmaf(d, d, dn);
        }

        // Warp reduction
        #pragma unroll
        for (int off = 16; off > 0; off >>= 1) {
            dp += __shfl_xor_sync(0xFFFFFFFFu, dp, off);
            dn += __shfl_xor_sync(0xFFFFFFFFu, dn, off);
        }

        if (lane == 0) {
            float loss = sqrtf(dp) - sqrtf(dn) + 1.0f;      // MARGIN = 1.0
            warp_acc += fmaxf(loss, 0.0f) * (1.0f / (float)BATCH);
        }
    }

    __shared__ float partial[WARPS_PER_BLOCK];
    if (lane == 0) partial[warp_in_block] = warp_acc;
    __syncthreads();

    // One fire-and-forget atomic per block (RED.E.ADD), after the PDL
    // dependency on the zeroing kernel is settled (long since complete).
    if (threadIdx.x == 0) {
        float acc = 0.0f;
        #pragma unroll
        for (int w = 0; w < WARPS_PER_BLOCK; w++) acc += partial[w];
#if __CUDA_ARCH__ >= 900
        cudaGridDependencySynchronize();
#endif
        atomicAdd(out, acc);
    }
}

extern "C" void kernel_launch(void* const* d_in, const int* in_sizes, int n_in,
                              void* d_out, int out_size) {
    const float4* anchor   = (const float4*)d_in[0];
    const float4* positive = (const float4*)d_in[1];
    const float4* negative = (const float4*)d_in[2];
    float* out = (float*)d_out;

    // Primary: zero the scalar output.
    zero_out_kernel<<<1, 1>>>(out);

    // Secondary: main kernel with programmatic dependent launch so its
    // launch/prologue overlaps the primary instead of serializing.
    cudaLaunchConfig_t cfg = {};
    cfg.gridDim  = dim3(GRID, 1, 1);
    cfg.blockDim = dim3(THREADS, 1, 1);
    cfg.dynamicSmemBytes = 0;
    cfg.stream = 0;  // same (legacy default) stream the harness captures

    cudaLaunchAttribute attrs[1];
    attrs[0].id = cudaLaunchAttributeProgrammaticStreamSerialization;
    attrs[0].val.programmaticStreamSerializationAllowed = 1;
    cfg.attrs = attrs;
    cfg.numAttrs = 1;

    cudaError_t err = cudaLaunchKernelEx(&cfg, triplet_loss_kernel,
                                         anchor, positive, negative, out);
    if (err != cudaSuccess) {
        // Fallback: plain sequential launch (exact R2 behavior).
        (void)cudaGetLastError();  // clear
        triplet_loss_kernel<<<GRID, THREADS>>>(anchor, positive, negative, out);
    }
}